// round 11
// baseline (speedup 1.0000x reference)
#include <cuda_runtime.h>
#include <math.h>

#define NB 4096
#define ND 128
#define TILE 128
#define KC 32
#define LDW (TILE + 4)
#define MAXM 64
#define MARGINF 0.2f

__device__ __align__(16) float g_sq[NB];
__device__ __align__(16) float g_partial[NB];
__device__ __align__(16) float g_sim[(size_t)NB * NB];  // 64 MB sim matrix

// Prep: squared norms. One warp per row.
__global__ void prep_kernel(const float* __restrict__ X) {
    int row = blockIdx.x * 8 + (threadIdx.x >> 5);
    int lane = threadIdx.x & 31;
    float4 v = ((const float4*)(X + (size_t)row * ND))[lane];
    float s = v.x * v.x + v.y * v.y + v.z * v.z + v.w * v.w;
    #pragma unroll
    for (int o = 16; o; o >>= 1) s += __shfl_xor_sync(0xffffffffu, s, o);
    if (lane == 0) g_sq[row] = s;
}

__device__ __forceinline__ float mksim(float si, float sj, float dot, bool mt) {
    float d2 = fmaxf(si + sj - 2.0f * dot, 0.0f);
    float s = (d2 == 0.0f) ? 0.0f : -sqrtf(d2);
    return mt ? s : s + MARGINF;
}

// ---------------- Kernel 2: symmetric tiled SGEMM -> sim matrix ----------------
// 1D triangular grid over 528 upper tiles; mirror-store the transposed block.
__global__ __launch_bounds__(256, 2)
void gemm_sim_kernel(const float* __restrict__ X, const int* __restrict__ labels) {
    // decode triangular tile index -> (bi, bj), bi <= bj, 32x32 tile grid
    int t = blockIdx.x;
    int bi = (int)((65.0f - sqrtf(4225.0f - 8.0f * (float)t)) * 0.5f);
    while ((bi + 1) * (65 - (bi + 1)) / 2 <= t) bi++;
    while (bi * (65 - bi) / 2 > t) bi--;
    int bj = bi + (t - bi * (65 - bi) / 2);

    extern __shared__ __align__(16) char smraw[];
    float* Asp = (float*)smraw;            // 2 * KC * LDW
    float* Bsp = Asp + 2 * KC * LDW;       // 2 * KC * LDW
    float* sqA = Bsp + 2 * KC * LDW;       // 128
    float* sqB = sqA + TILE;               // 128
    int*   lbA = (int*)(sqB + TILE);       // 128
    int*   lbB = lbA + TILE;               // 128

    int tid = threadIdx.x;
    int rowA = bi * TILE, rowB = bj * TILE;

    if (tid < 128) {
        sqA[tid] = g_sq[rowA + tid];
        lbA[tid] = labels[rowA + tid];
    } else {
        int tt = tid - 128;
        sqB[tt] = g_sq[rowB + tt];
        lbB[tt] = labels[rowB + tt];
    }

    auto load_chunk = [&](float* dst, int rowbase, int k0) {
        #pragma unroll
        for (int it = 0; it < 4; it++) {
            int idx = tid + 256 * it;
            int m = idx >> 3, q = idx & 7;
            float4 v = *(const float4*)(X + (size_t)(rowbase + m) * ND + k0 + 4 * q);
            dst[(4 * q + 0) * LDW + m] = v.x;
            dst[(4 * q + 1) * LDW + m] = v.y;
            dst[(4 * q + 2) * LDW + m] = v.z;
            dst[(4 * q + 3) * LDW + m] = v.w;
        }
    };

    load_chunk(Asp, rowA, 0);
    load_chunk(Bsp, rowB, 0);

    int wid = tid >> 5, lane = tid & 31;
    int mbase = (wid & 3) * 32 + (lane >> 3) * 8;
    int nbase = (wid >> 2) * 64 + (lane & 7) * 8;

    float acc[8][8];
    #pragma unroll
    for (int r = 0; r < 8; r++)
        #pragma unroll
        for (int p = 0; p < 8; p++) acc[r][p] = 0.0f;

    __syncthreads();
    #pragma unroll
    for (int ch = 0; ch < 4; ch++) {
        int cur = ch & 1, nxt = cur ^ 1;
        if (ch < 3) {
            load_chunk(Asp + nxt * KC * LDW, rowA, (ch + 1) * KC);
            load_chunk(Bsp + nxt * KC * LDW, rowB, (ch + 1) * KC);
        }
        const float* Ac = Asp + cur * KC * LDW;
        const float* Bc = Bsp + cur * KC * LDW;
        #pragma unroll
        for (int k = 0; k < KC; k++) {
            float4 a0 = *(const float4*)(Ac + k * LDW + mbase);
            float4 a1 = *(const float4*)(Ac + k * LDW + mbase + 4);
            float4 b0 = *(const float4*)(Bc + k * LDW + nbase);
            float4 b1 = *(const float4*)(Bc + k * LDW + nbase + 4);
            float av[8] = {a0.x, a0.y, a0.z, a0.w, a1.x, a1.y, a1.z, a1.w};
            float bv[8] = {b0.x, b0.y, b0.z, b0.w, b1.x, b1.y, b1.z, b1.w};
            #pragma unroll
            for (int r = 0; r < 8; r++)
                #pragma unroll
                for (int p = 0; p < 8; p++)
                    acc[r][p] = fmaf(av[r], bv[p], acc[r][p]);
        }
        __syncthreads();
    }

    float vals[8][8];
    #pragma unroll
    for (int r = 0; r < 8; r++) {
        int ml = mbase + r;
        float sm_ = sqA[ml];
        int lm = lbA[ml];
        #pragma unroll
        for (int p = 0; p < 8; p++) {
            int nl = nbase + p;
            vals[r][p] = mksim(sm_, sqB[nl], acc[r][p], lm == lbB[nl]);
        }
        float* dst = g_sim + (size_t)(rowA + ml) * NB + rowB + nbase;
        *(float4*)dst       = make_float4(vals[r][0], vals[r][1], vals[r][2], vals[r][3]);
        *(float4*)(dst + 4) = make_float4(vals[r][4], vals[r][5], vals[r][6], vals[r][7]);
    }
    if (bi != bj) {
        #pragma unroll
        for (int p = 0; p < 8; p++) {
            float* dst = g_sim + (size_t)(rowB + nbase + p) * NB + rowA + mbase;
            *(float4*)dst       = make_float4(vals[0][p], vals[1][p], vals[2][p], vals[3][p]);
            *(float4*)(dst + 4) = make_float4(vals[4][p], vals[5][p], vals[6][p], vals[7][p]);
        }
    }
}

// ---------------- Kernel 3: per-row rank-aware selection ----------------
// One row per CTA, 256 threads. Per-warp top-k extraction (no block barriers)
// + single-thread 8-way merge. Only 3 block barriers total.
__device__ __forceinline__ int gjf(int tid, int q) {
    return 4 * tid + 1024 * (q >> 2) + (q & 3);
}

__global__ __launch_bounds__(256)
void phaseB_kernel(const int* __restrict__ labels) {
    __shared__ float vm[MAXM];
    __shared__ int jm[MAXM];
    __shared__ int cnt[MAXM];
    __shared__ float wv[8][MAXM];   // per-warp top-k values (desc)
    __shared__ int   wj[8][MAXM];   // packed (idx<<1)|match
    __shared__ int mcount;

    const float NEG_INF = __int_as_float(0xff800000);
    const int   PMAX = 0x7fffffff;
    int tid = threadIdx.x, lane = tid & 31, wid = tid >> 5;
    int row = blockIdx.x;
    const float* simr = g_sim + (size_t)row * NB;
    int lr = labels[row];
    if (tid == 0) mcount = 0;
    __syncthreads();

    float ls[16];
    unsigned mrow = 0;
    #pragma unroll
    for (int t = 0; t < 4; t++) {
        int j4 = tid + 256 * t;
        float4 s4 = *(const float4*)(simr + 4 * (size_t)j4);
        int4 l4 = *(const int4*)(labels + 4 * j4);
        int b = 4 * t;
        ls[b + 0] = s4.x; ls[b + 1] = s4.y; ls[b + 2] = s4.z; ls[b + 3] = s4.w;
        if (l4.x == lr) mrow |= 1u << (b + 0);
        if (l4.y == lr) mrow |= 1u << (b + 1);
        if (l4.z == lr) mrow |= 1u << (b + 2);
        if (l4.w == lr) mrow |= 1u << (b + 3);
    }

    // Gather matched elements.
    #pragma unroll
    for (int q = 0; q < 16; q++) {
        if ((mrow >> q) & 1u) {
            int p = atomicAdd(&mcount, 1);
            if (p < MAXM) { jm[p] = gjf(tid, q); vm[p] = ls[q]; cnt[p] = 0; }
        }
    }
    __syncthreads();
    int k = mcount;
    if (k > MAXM) k = MAXM;

    // Count-based ranks for matched elements (rank = cnt+1, stable ties).
    for (int m = 0; m < k; m++) {
        float vmv = vm[m];
        int jmi = jm[m];
        int c = 0;
        #pragma unroll
        for (int q = 0; q < 16; q++)
            c += (ls[q] > vmv || (ls[q] == vmv && gjf(tid, q) < jmi)) ? 1 : 0;
        c = __reduce_add_sync(0xffffffffu, c);
        if (lane == 0) atomicAdd(&cnt[m], c);
    }

    // Per-warp top-k extraction, warp-synchronous, no block barriers.
    // Per-lane running max, warp shfl-reduce each step, owner lane rescans.
    {
        float lval = NEG_INF;
        int lpack = PMAX, lq = 0;
        #pragma unroll
        for (int q = 0; q < 16; q++) {
            float v = ls[q];
            int p = (gjf(tid, q) << 1) | ((mrow >> q) & 1);
            if (v > lval || (v == lval && p < lpack)) { lval = v; lpack = p; lq = q; }
        }
        for (int e = 0; e < k; e++) {
            float bv = lval;
            int bp = lpack;
            #pragma unroll
            for (int o = 16; o; o >>= 1) {
                float ov = __shfl_xor_sync(0xffffffffu, bv, o);
                int op = __shfl_xor_sync(0xffffffffu, bp, o);
                if (ov > bv || (ov == bv && op < bp)) { bv = ov; bp = op; }
            }
            if (lane == 0) { wv[wid][e] = bv; wj[wid][e] = bp; }
            if (lpack == bp) {  // this lane owned the winner: clear + rescan
                ls[lq] = NEG_INF;
                lval = NEG_INF; lpack = PMAX; lq = 0;
                #pragma unroll
                for (int q = 0; q < 16; q++) {
                    float v = ls[q];
                    int p = (gjf(tid, q) << 1) | ((mrow >> q) & 1);
                    if (v > lval || (v == lval && p < lpack)) { lval = v; lpack = p; lq = q; }
                }
            }
        }
    }
    __syncthreads();

    // Thread 0: 8-way merge of sorted warp lists -> global top-k, fp term;
    // then fn term from count-ranks; write per-row partial.
    if (tid == 0) {
        int h[8] = {0, 0, 0, 0, 0, 0, 0, 0};
        float kf = (float)k;
        float fp_acc = 0.0f;
        for (int e = 1; e <= k; e++) {
            float bv = NEG_INF;
            int bp = PMAX, bw = 0;
            #pragma unroll
            for (int w = 0; w < 8; w++) {
                if (h[w] < k) {
                    float v = wv[w][h[w]];
                    int p = wj[w][h[w]];
                    if (v > bv || (v == bv && p < bp)) { bv = v; bp = p; bw = w; }
                }
            }
            h[bw]++;
            if (!(bp & 1))  // false positive at rank e
                fp_acc += bv * (0.5f + (kf - (float)e + 1.0f) / kf * 0.5f);
        }
        float fn_acc = 0.0f;
        float nf = (float)NB;
        for (int m = 0; m < k; m++) {
            int rank = cnt[m] + 1;
            if (rank > k)
                fn_acc += vm[m] * (0.5f + ((float)rank - kf) / (nf - kf) * 0.5f);
        }
        g_partial[row] = fp_acc - fn_acc;
    }
}

// Deterministic tree reduction of the 4096 per-row partials.
__global__ void out_kernel(float* out) {
    __shared__ double red[256];
    int tid = threadIdx.x;
    double s = 0.0;
    #pragma unroll
    for (int t = 0; t < 16; t++) s += (double)g_partial[tid + 256 * t];
    red[tid] = s;
    __syncthreads();
    for (int o = 128; o; o >>= 1) {
        if (tid < o) red[tid] += red[tid + o];
        __syncthreads();
    }
    if (tid == 0) out[0] = (float)red[0];
}

extern "C" void kernel_launch(void* const* d_in, const int* in_sizes, int n_in,
                              void* d_out, int out_size) {
    const float* X = (const float*)d_in[0];
    const int* labels = (const int*)d_in[1];
    float* out = (float*)d_out;

    size_t shmem = (size_t)4 * KC * LDW * 4 + 2 * TILE * 4 + 2 * TILE * 4;
    cudaFuncSetAttribute(gemm_sim_kernel,
                         cudaFuncAttributeMaxDynamicSharedMemorySize, (int)shmem);

    prep_kernel<<<NB / 8, 256>>>(X);
    gemm_sim_kernel<<<528, 256, shmem>>>(X, labels);
    phaseB_kernel<<<NB, 256>>>(labels);
    out_kernel<<<1, 256>>>(out);
}

// round 14
// speedup vs baseline: 1.0483x; 1.0483x over previous
#include <cuda_runtime.h>
#include <cuda_bf16.h>
#include <math.h>

#define NB 4096
#define ND 128
#define LDA 40
#define MAXM 64
#define MARGINF 0.2f

__device__ __align__(16) float g_sq[NB];
__device__ __align__(16) float g_partial[NB];
__device__ __align__(16) float g_sim[(size_t)NB * NB];            // 64 MB
__device__ __align__(16) __nv_bfloat16 g_Xhi[(size_t)NB * ND];    // 1 MB
__device__ __align__(16) __nv_bfloat16 g_Xlo[(size_t)NB * ND];    // 1 MB

// ---------------- Kernel 1: norms + bf16 hi/lo split ----------------
__global__ void prep_kernel(const float* __restrict__ X) {
    int row = blockIdx.x * 8 + (threadIdx.x >> 5);
    int lane = threadIdx.x & 31;
    float4 v = ((const float4*)(X + (size_t)row * ND))[lane];
    float s = v.x * v.x + v.y * v.y + v.z * v.z + v.w * v.w;
    #pragma unroll
    for (int o = 16; o; o >>= 1) s += __shfl_xor_sync(0xffffffffu, s, o);
    if (lane == 0) g_sq[row] = s;
    __nv_bfloat16 h0 = __float2bfloat16(v.x), h1 = __float2bfloat16(v.y);
    __nv_bfloat16 h2 = __float2bfloat16(v.z), h3 = __float2bfloat16(v.w);
    __nv_bfloat16 l0 = __float2bfloat16(v.x - __bfloat162float(h0));
    __nv_bfloat16 l1 = __float2bfloat16(v.y - __bfloat162float(h1));
    __nv_bfloat16 l2 = __float2bfloat16(v.z - __bfloat162float(h2));
    __nv_bfloat16 l3 = __float2bfloat16(v.w - __bfloat162float(h3));
    size_t base = (size_t)row * ND + 4 * lane;
    ((__nv_bfloat162*)(g_Xhi + base))[0] = __nv_bfloat162(h0, h1);
    ((__nv_bfloat162*)(g_Xhi + base))[1] = __nv_bfloat162(h2, h3);
    ((__nv_bfloat162*)(g_Xlo + base))[0] = __nv_bfloat162(l0, l1);
    ((__nv_bfloat162*)(g_Xlo + base))[1] = __nv_bfloat162(l2, l3);
}

__device__ __forceinline__ float mksim(float si, float sj, float dot, bool mt) {
    float d2 = fmaxf(si + sj - 2.0f * dot, 0.0f);
    float s = (d2 == 0.0f) ? 0.0f : -sqrtf(d2);
    return mt ? s : s + MARGINF;
}

// ---------------- Kernel 2: mma.sync bf16 split-GEMM -> sim ----------------
// 128x128 tile/CTA, 256 thr, warp tile 32x64 (2 m16 x 8 n8), K=384 (3 bf16
// split terms: hi.hi + hi.lo + lo.hi), 12 double-buffered K=32 chunks.
__global__ __launch_bounds__(256, 2)
void gemm_mma_kernel(const int* __restrict__ labels) {
    __shared__ __align__(16) __nv_bfloat16 Asm[2][128 * LDA];
    __shared__ __align__(16) __nv_bfloat16 Bsm[2][128 * LDA];
    __shared__ float sqA[128], sqB[128];
    __shared__ int lbA[128], lbB[128];

    int tid = threadIdx.x, lane = tid & 31, wid = tid >> 5;
    int rowA = blockIdx.y * 128, rowB = blockIdx.x * 128;

    if (tid < 128) {
        sqA[tid] = g_sq[rowA + tid];
        lbA[tid] = labels[rowA + tid];
    } else {
        int t = tid - 128;
        sqB[t] = g_sq[rowB + t];
        lbB[t] = labels[rowB + t];
    }

    int lrow = tid >> 1, lhalf = tid & 1;   // loader: row, 16-col half
    int wm = (wid & 3) * 32, wn = (wid >> 2) * 64;
    // ldmatrix per-lane offsets (elements)
    int ar = (lane & 7) + 8 * ((lane >> 3) & 1);   // A: row within 16
    int ac = 8 * (lane >> 4);                      // A: col 0/8
    int br = (lane & 7) + 8 * ((lane >> 4) & 1);   // B: n within 16
    int bc = 8 * ((lane >> 3) & 1);                // B: col 0/8

    float d[2][8][4];
    #pragma unroll
    for (int mi = 0; mi < 2; mi++)
        #pragma unroll
        for (int nj = 0; nj < 8; nj++)
            #pragma unroll
            for (int q = 0; q < 4; q++) d[mi][nj][q] = 0.0f;

    uint4 arg0, arg1, brg0, brg1;
    {   // chunk 0: seg 0 -> hi . hi
        const uint4* As = (const uint4*)(g_Xhi + (size_t)(rowA + lrow) * ND + 16 * lhalf);
        const uint4* Bs = (const uint4*)(g_Xhi + (size_t)(rowB + lrow) * ND + 16 * lhalf);
        arg0 = As[0]; arg1 = As[1];
        brg0 = Bs[0]; brg1 = Bs[1];
    }
    ((uint4*)(Asm[0] + lrow * LDA + 16 * lhalf))[0] = arg0;
    ((uint4*)(Asm[0] + lrow * LDA + 16 * lhalf))[1] = arg1;
    ((uint4*)(Bsm[0] + lrow * LDA + 16 * lhalf))[0] = brg0;
    ((uint4*)(Bsm[0] + lrow * LDA + 16 * lhalf))[1] = brg1;
    __syncthreads();

    #pragma unroll
    for (int c = 0; c < 12; c++) {
        int cur = c & 1;
        if (c < 11) {   // prefetch next chunk into registers
            int cn = c + 1;
            int seg = cn >> 2, k0 = (cn & 3) * 32;
            const __nv_bfloat16* Aps = (seg < 2) ? g_Xhi : g_Xlo;   // hi,hi,lo
            const __nv_bfloat16* Bps = (seg == 1) ? g_Xlo : g_Xhi;  // hi,lo,hi
            const uint4* As = (const uint4*)(Aps + (size_t)(rowA + lrow) * ND + k0 + 16 * lhalf);
            const uint4* Bs = (const uint4*)(Bps + (size_t)(rowB + lrow) * ND + k0 + 16 * lhalf);
            arg0 = As[0]; arg1 = As[1];
            brg0 = Bs[0]; brg1 = Bs[1];
        }
        unsigned sA = (unsigned)__cvta_generic_to_shared(Asm[cur]);
        unsigned sB = (unsigned)__cvta_generic_to_shared(Bsm[cur]);
        #pragma unroll
        for (int ks = 0; ks < 2; ks++) {
            unsigned a_[2][4], b_[8][2];
            #pragma unroll
            for (int mi = 0; mi < 2; mi++) {
                unsigned ad = sA + 2u * (unsigned)((wm + mi * 16 + ar) * LDA + ks * 16 + ac);
                asm volatile(
                    "ldmatrix.sync.aligned.m8n8.x4.shared.b16 {%0,%1,%2,%3}, [%4];"
                    : "=r"(a_[mi][0]), "=r"(a_[mi][1]), "=r"(a_[mi][2]), "=r"(a_[mi][3])
                    : "r"(ad));
            }
            #pragma unroll
            for (int np = 0; np < 4; np++) {
                unsigned bd = sB + 2u * (unsigned)((wn + np * 16 + br) * LDA + ks * 16 + bc);
                asm volatile(
                    "ldmatrix.sync.aligned.m8n8.x4.shared.b16 {%0,%1,%2,%3}, [%4];"
                    : "=r"(b_[2 * np][0]), "=r"(b_[2 * np][1]),
                      "=r"(b_[2 * np + 1][0]), "=r"(b_[2 * np + 1][1])
                    : "r"(bd));
            }
            #pragma unroll
            for (int mi = 0; mi < 2; mi++)
                #pragma unroll
                for (int nj = 0; nj < 8; nj++)
                    asm volatile(
                        "mma.sync.aligned.m16n8k16.row.col.f32.bf16.bf16.f32 "
                        "{%0,%1,%2,%3},{%4,%5,%6,%7},{%8,%9},{%0,%1,%2,%3};"
                        : "+f"(d[mi][nj][0]), "+f"(d[mi][nj][1]),
                          "+f"(d[mi][nj][2]), "+f"(d[mi][nj][3])
                        : "r"(a_[mi][0]), "r"(a_[mi][1]), "r"(a_[mi][2]), "r"(a_[mi][3]),
                          "r"(b_[nj][0]), "r"(b_[nj][1]));
        }
        if (c < 11) {
            int nxt = cur ^ 1;
            ((uint4*)(Asm[nxt] + lrow * LDA + 16 * lhalf))[0] = arg0;
            ((uint4*)(Asm[nxt] + lrow * LDA + 16 * lhalf))[1] = arg1;
            ((uint4*)(Bsm[nxt] + lrow * LDA + 16 * lhalf))[0] = brg0;
            ((uint4*)(Bsm[nxt] + lrow * LDA + 16 * lhalf))[1] = brg1;
        }
        __syncthreads();
    }

    // Epilogue: sim + store. d0,d1 -> row gid; d2,d3 -> row gid+8.
    int gid = lane >> 2, tig = lane & 3;
    #pragma unroll
    for (int mi = 0; mi < 2; mi++) {
        #pragma unroll
        for (int half = 0; half < 2; half++) {
            int ml = wm + mi * 16 + gid + 8 * half;
            float sa = sqA[ml];
            int la = lbA[ml];
            float* dst = g_sim + (size_t)(rowA + ml) * NB + rowB;
            #pragma unroll
            for (int nj = 0; nj < 8; nj++) {
                int nl = wn + nj * 8 + 2 * tig;
                float2 o;
                o.x = mksim(sa, sqB[nl],     d[mi][nj][2 * half],     la == lbB[nl]);
                o.y = mksim(sa, sqB[nl + 1], d[mi][nj][2 * half + 1], la == lbB[nl + 1]);
                *(float2*)(dst + nl) = o;
            }
        }
    }
}

// ---------------- Kernel 3: per-row rank-aware selection ----------------
__device__ __forceinline__ int gjf(int tid, int q) {
    return 4 * tid + 1024 * (q >> 2) + (q & 3);
}

__global__ __launch_bounds__(256)
void phaseB_kernel(const int* __restrict__ labels) {
    __shared__ float vm[MAXM];
    __shared__ int jm[MAXM];
    __shared__ int cnt[MAXM];
    __shared__ float wv[8][MAXM];
    __shared__ int   wj[8][MAXM];
    __shared__ int mcount;

    const float NEG_INF = __int_as_float(0xff800000);
    const int   PMAX = 0x7fffffff;
    int tid = threadIdx.x, lane = tid & 31, wid = tid >> 5;
    int row = blockIdx.x;
    const float* simr = g_sim + (size_t)row * NB;
    int lr = labels[row];
    if (tid == 0) mcount = 0;
    __syncthreads();

    float ls[16];
    unsigned mrow = 0;
    #pragma unroll
    for (int t = 0; t < 4; t++) {
        int j4 = tid + 256 * t;
        float4 s4 = *(const float4*)(simr + 4 * (size_t)j4);
        int4 l4 = *(const int4*)(labels + 4 * j4);
        int b = 4 * t;
        ls[b + 0] = s4.x; ls[b + 1] = s4.y; ls[b + 2] = s4.z; ls[b + 3] = s4.w;
        if (l4.x == lr) mrow |= 1u << (b + 0);
        if (l4.y == lr) mrow |= 1u << (b + 1);
        if (l4.z == lr) mrow |= 1u << (b + 2);
        if (l4.w == lr) mrow |= 1u << (b + 3);
    }

    #pragma unroll
    for (int q = 0; q < 16; q++) {
        if ((mrow >> q) & 1u) {
            int p = atomicAdd(&mcount, 1);
            if (p < MAXM) { jm[p] = gjf(tid, q); vm[p] = ls[q]; cnt[p] = 0; }
        }
    }
    __syncthreads();
    int k = mcount;
    if (k > MAXM) k = MAXM;

    for (int m = 0; m < k; m++) {
        float vmv = vm[m];
        int jmi = jm[m];
        int c = 0;
        #pragma unroll
        for (int q = 0; q < 16; q++)
            c += (ls[q] > vmv || (ls[q] == vmv && gjf(tid, q) < jmi)) ? 1 : 0;
        c = __reduce_add_sync(0xffffffffu, c);
        if (lane == 0) atomicAdd(&cnt[m], c);
    }

    {
        float lval = NEG_INF;
        int lpack = PMAX, lq = 0;
        #pragma unroll
        for (int q = 0; q < 16; q++) {
            float v = ls[q];
            int p = (gjf(tid, q) << 1) | ((mrow >> q) & 1);
            if (v > lval || (v == lval && p < lpack)) { lval = v; lpack = p; lq = q; }
        }
        for (int e = 0; e < k; e++) {
            float bv = lval;
            int bp = lpack;
            #pragma unroll
            for (int o = 16; o; o >>= 1) {
                float ov = __shfl_xor_sync(0xffffffffu, bv, o);
                int op = __shfl_xor_sync(0xffffffffu, bp, o);
                if (ov > bv || (ov == bv && op < bp)) { bv = ov; bp = op; }
            }
            if (lane == 0) { wv[wid][e] = bv; wj[wid][e] = bp; }
            if (lpack == bp) {
                ls[lq] = NEG_INF;
                lval = NEG_INF; lpack = PMAX; lq = 0;
                #pragma unroll
                for (int q = 0; q < 16; q++) {
                    float v = ls[q];
                    int p = (gjf(tid, q) << 1) | ((mrow >> q) & 1);
                    if (v > lval || (v == lval && p < lpack)) { lval = v; lpack = p; lq = q; }
                }
            }
        }
    }
    __syncthreads();

    if (tid == 0) {
        int h[8] = {0, 0, 0, 0, 0, 0, 0, 0};
        float kf = (float)k;
        float fp_acc = 0.0f;
        for (int e = 1; e <= k; e++) {
            float bv = NEG_INF;
            int bp = PMAX, bw = 0;
            #pragma unroll
            for (int w = 0; w < 8; w++) {
                if (h[w] < k) {
                    float v = wv[w][h[w]];
                    int p = wj[w][h[w]];
                    if (v > bv || (v == bv && p < bp)) { bv = v; bp = p; bw = w; }
                }
            }
            h[bw]++;
            if (!(bp & 1))
                fp_acc += bv * (0.5f + (kf - (float)e + 1.0f) / kf * 0.5f);
        }
        float fn_acc = 0.0f;
        float nf = (float)NB;
        for (int m = 0; m < k; m++) {
            int rank = cnt[m] + 1;
            if (rank > k)
                fn_acc += vm[m] * (0.5f + ((float)rank - kf) / (nf - kf) * 0.5f);
        }
        g_partial[row] = fp_acc - fn_acc;
    }
}

__global__ void out_kernel(float* out) {
    __shared__ double red[256];
    int tid = threadIdx.x;
    double s = 0.0;
    #pragma unroll
    for (int t = 0; t < 16; t++) s += (double)g_partial[tid + 256 * t];
    red[tid] = s;
    __syncthreads();
    for (int o = 128; o; o >>= 1) {
        if (tid < o) red[tid] += red[tid + o];
        __syncthreads();
    }
    if (tid == 0) out[0] = (float)red[0];
}

extern "C" void kernel_launch(void* const* d_in, const int* in_sizes, int n_in,
                              void* d_out, int out_size) {
    const float* X = (const float*)d_in[0];
    const int* labels = (const int*)d_in[1];
    float* out = (float*)d_out;

    prep_kernel<<<NB / 8, 256>>>(X);
    gemm_mma_kernel<<<dim3(NB / 128, NB / 128), 256>>>(labels);
    phaseB_kernel<<<NB, 256>>>(labels);
    out_kernel<<<1, 256>>>(out);
}

// round 15
// speedup vs baseline: 1.1512x; 1.0982x over previous
#include <cuda_runtime.h>
#include <cuda_bf16.h>
#include <math.h>

#define NB 4096
#define ND 128
#define LDA 40
#define MAXM 64
#define MARGINF 0.2f

__device__ __align__(16) float g_sq[NB];
__device__ __align__(16) float g_partial[NB];
__device__ __align__(16) float g_sim[(size_t)NB * NB];            // 64 MB
__device__ __align__(16) __nv_bfloat16 g_Xhi[(size_t)NB * ND];    // 1 MB
__device__ __align__(16) __nv_bfloat16 g_Xlo[(size_t)NB * ND];    // 1 MB

// ---------------- Kernel 1: norms + bf16 hi/lo split ----------------
__global__ void prep_kernel(const float* __restrict__ X) {
    int row = blockIdx.x * 8 + (threadIdx.x >> 5);
    int lane = threadIdx.x & 31;
    float4 v = ((const float4*)(X + (size_t)row * ND))[lane];
    float s = v.x * v.x + v.y * v.y + v.z * v.z + v.w * v.w;
    #pragma unroll
    for (int o = 16; o; o >>= 1) s += __shfl_xor_sync(0xffffffffu, s, o);
    if (lane == 0) g_sq[row] = s;
    __nv_bfloat16 h0 = __float2bfloat16(v.x), h1 = __float2bfloat16(v.y);
    __nv_bfloat16 h2 = __float2bfloat16(v.z), h3 = __float2bfloat16(v.w);
    __nv_bfloat16 l0 = __float2bfloat16(v.x - __bfloat162float(h0));
    __nv_bfloat16 l1 = __float2bfloat16(v.y - __bfloat162float(h1));
    __nv_bfloat16 l2 = __float2bfloat16(v.z - __bfloat162float(h2));
    __nv_bfloat16 l3 = __float2bfloat16(v.w - __bfloat162float(h3));
    size_t base = (size_t)row * ND + 4 * lane;
    ((__nv_bfloat162*)(g_Xhi + base))[0] = __nv_bfloat162(h0, h1);
    ((__nv_bfloat162*)(g_Xhi + base))[1] = __nv_bfloat162(h2, h3);
    ((__nv_bfloat162*)(g_Xlo + base))[0] = __nv_bfloat162(l0, l1);
    ((__nv_bfloat162*)(g_Xlo + base))[1] = __nv_bfloat162(l2, l3);
}

__device__ __forceinline__ float mksim(float si, float sj, float dot, bool mt) {
    float d2 = fmaxf(si + sj - 2.0f * dot, 0.0f);
    float s = (d2 == 0.0f) ? 0.0f : -sqrtf(d2);
    return mt ? s : s + MARGINF;
}

// ---------------- Kernel 2: mma.sync bf16 split-GEMM -> sim ----------------
// Symmetric: 528 upper-triangular 128x128 tiles; off-diagonal tiles also
// mirror-store the transpose. 256 thr, warp tile 32x64, K=384 (hi.hi +
// hi.lo + lo.hi), 12 double-buffered K=32 chunks.
__global__ __launch_bounds__(256, 2)
void gemm_mma_kernel(const int* __restrict__ labels) {
    // decode triangular index -> (bi, bj), bi <= bj, 32x32 tile grid
    int t = blockIdx.x;
    int bi = 0;
    while ((bi + 1) * (65 - (bi + 1)) / 2 <= t) bi++;
    int bj = bi + (t - bi * (65 - bi) / 2);

    __shared__ __align__(16) __nv_bfloat16 Asm[2][128 * LDA];
    __shared__ __align__(16) __nv_bfloat16 Bsm[2][128 * LDA];
    __shared__ float sqA[128], sqB[128];
    __shared__ int lbA[128], lbB[128];

    int tid = threadIdx.x, lane = tid & 31, wid = tid >> 5;
    int rowA = bi * 128, rowB = bj * 128;

    if (tid < 128) {
        sqA[tid] = g_sq[rowA + tid];
        lbA[tid] = labels[rowA + tid];
    } else {
        int tt = tid - 128;
        sqB[tt] = g_sq[rowB + tt];
        lbB[tt] = labels[rowB + tt];
    }

    int lrow = tid >> 1, lhalf = tid & 1;   // loader: row, 16-col half
    int wm = (wid & 3) * 32, wn = (wid >> 2) * 64;
    int ar = (lane & 7) + 8 * ((lane >> 3) & 1);   // A: row within 16
    int ac = 8 * (lane >> 4);                      // A: col 0/8
    int br = (lane & 7) + 8 * ((lane >> 4) & 1);   // B: n within 16
    int bc = 8 * ((lane >> 3) & 1);                // B: col 0/8

    float d[2][8][4];
    #pragma unroll
    for (int mi = 0; mi < 2; mi++)
        #pragma unroll
        for (int nj = 0; nj < 8; nj++)
            #pragma unroll
            for (int q = 0; q < 4; q++) d[mi][nj][q] = 0.0f;

    uint4 arg0, arg1, brg0, brg1;
    {   // chunk 0: hi . hi
        const uint4* As = (const uint4*)(g_Xhi + (size_t)(rowA + lrow) * ND + 16 * lhalf);
        const uint4* Bs = (const uint4*)(g_Xhi + (size_t)(rowB + lrow) * ND + 16 * lhalf);
        arg0 = As[0]; arg1 = As[1];
        brg0 = Bs[0]; brg1 = Bs[1];
    }
    ((uint4*)(Asm[0] + lrow * LDA + 16 * lhalf))[0] = arg0;
    ((uint4*)(Asm[0] + lrow * LDA + 16 * lhalf))[1] = arg1;
    ((uint4*)(Bsm[0] + lrow * LDA + 16 * lhalf))[0] = brg0;
    ((uint4*)(Bsm[0] + lrow * LDA + 16 * lhalf))[1] = brg1;
    __syncthreads();

    #pragma unroll
    for (int c = 0; c < 12; c++) {
        int cur = c & 1;
        if (c < 11) {   // prefetch next chunk into registers
            int cn = c + 1;
            int seg = cn >> 2, k0 = (cn & 3) * 32;
            const __nv_bfloat16* Aps = (seg < 2) ? g_Xhi : g_Xlo;   // hi,hi,lo
            const __nv_bfloat16* Bps = (seg == 1) ? g_Xlo : g_Xhi;  // hi,lo,hi
            const uint4* As = (const uint4*)(Aps + (size_t)(rowA + lrow) * ND + k0 + 16 * lhalf);
            const uint4* Bs = (const uint4*)(Bps + (size_t)(rowB + lrow) * ND + k0 + 16 * lhalf);
            arg0 = As[0]; arg1 = As[1];
            brg0 = Bs[0]; brg1 = Bs[1];
        }
        unsigned sA = (unsigned)__cvta_generic_to_shared(Asm[cur]);
        unsigned sB = (unsigned)__cvta_generic_to_shared(Bsm[cur]);
        #pragma unroll
        for (int ks = 0; ks < 2; ks++) {
            unsigned a_[2][4], b_[8][2];
            #pragma unroll
            for (int mi = 0; mi < 2; mi++) {
                unsigned ad = sA + 2u * (unsigned)((wm + mi * 16 + ar) * LDA + ks * 16 + ac);
                asm volatile(
                    "ldmatrix.sync.aligned.m8n8.x4.shared.b16 {%0,%1,%2,%3}, [%4];"
                    : "=r"(a_[mi][0]), "=r"(a_[mi][1]), "=r"(a_[mi][2]), "=r"(a_[mi][3])
                    : "r"(ad));
            }
            #pragma unroll
            for (int np = 0; np < 4; np++) {
                unsigned bd = sB + 2u * (unsigned)((wn + np * 16 + br) * LDA + ks * 16 + bc);
                asm volatile(
                    "ldmatrix.sync.aligned.m8n8.x4.shared.b16 {%0,%1,%2,%3}, [%4];"
                    : "=r"(b_[2 * np][0]), "=r"(b_[2 * np][1]),
                      "=r"(b_[2 * np + 1][0]), "=r"(b_[2 * np + 1][1])
                    : "r"(bd));
            }
            #pragma unroll
            for (int mi = 0; mi < 2; mi++)
                #pragma unroll
                for (int nj = 0; nj < 8; nj++)
                    asm volatile(
                        "mma.sync.aligned.m16n8k16.row.col.f32.bf16.bf16.f32 "
                        "{%0,%1,%2,%3},{%4,%5,%6,%7},{%8,%9},{%0,%1,%2,%3};"
                        : "+f"(d[mi][nj][0]), "+f"(d[mi][nj][1]),
                          "+f"(d[mi][nj][2]), "+f"(d[mi][nj][3])
                        : "r"(a_[mi][0]), "r"(a_[mi][1]), "r"(a_[mi][2]), "r"(a_[mi][3]),
                          "r"(b_[nj][0]), "r"(b_[nj][1]));
        }
        if (c < 11) {
            int nxt = cur ^ 1;
            ((uint4*)(Asm[nxt] + lrow * LDA + 16 * lhalf))[0] = arg0;
            ((uint4*)(Asm[nxt] + lrow * LDA + 16 * lhalf))[1] = arg1;
            ((uint4*)(Bsm[nxt] + lrow * LDA + 16 * lhalf))[0] = brg0;
            ((uint4*)(Bsm[nxt] + lrow * LDA + 16 * lhalf))[1] = brg1;
        }
        __syncthreads();
    }

    // Epilogue: sim + normal (coalesced) store, plus mirror store if bi != bj.
    int gid = lane >> 2, tig = lane & 3;
    #pragma unroll
    for (int mi = 0; mi < 2; mi++) {
        #pragma unroll
        for (int half = 0; half < 2; half++) {
            int ml = wm + mi * 16 + gid + 8 * half;
            float sa = sqA[ml];
            int la = lbA[ml];
            float* dst = g_sim + (size_t)(rowA + ml) * NB + rowB;
            #pragma unroll
            for (int nj = 0; nj < 8; nj++) {
                int nl = wn + nj * 8 + 2 * tig;
                float2 o;
                o.x = mksim(sa, sqB[nl],     d[mi][nj][2 * half],     la == lbB[nl]);
                o.y = mksim(sa, sqB[nl + 1], d[mi][nj][2 * half + 1], la == lbB[nl + 1]);
                *(float2*)(dst + nl) = o;
                if (bi != bj) {   // mirror: sim[rowB+nl][rowA+ml] = same values
                    g_sim[(size_t)(rowB + nl) * NB + rowA + ml] = o.x;
                    g_sim[(size_t)(rowB + nl + 1) * NB + rowA + ml] = o.y;
                }
            }
        }
    }
}

// ---------------- Kernel 3: per-row rank-aware selection ----------------
__device__ __forceinline__ int gjf(int tid, int q) {
    return 4 * tid + 1024 * (q >> 2) + (q & 3);
}

__global__ __launch_bounds__(256)
void phaseB_kernel(const int* __restrict__ labels) {
    __shared__ float vm[MAXM];
    __shared__ int jm[MAXM];
    __shared__ int cnt[MAXM];
    __shared__ float wv[8][MAXM];
    __shared__ int   wj[8][MAXM];
    __shared__ int mcount;

    const float NEG_INF = __int_as_float(0xff800000);
    const int   PMAX = 0x7fffffff;
    int tid = threadIdx.x, lane = tid & 31, wid = tid >> 5;
    int row = blockIdx.x;
    const float* simr = g_sim + (size_t)row * NB;
    int lr = labels[row];
    if (tid == 0) mcount = 0;
    __syncthreads();

    float ls[16];
    unsigned mrow = 0;
    #pragma unroll
    for (int t = 0; t < 4; t++) {
        int j4 = tid + 256 * t;
        float4 s4 = *(const float4*)(simr + 4 * (size_t)j4);
        int4 l4 = *(const int4*)(labels + 4 * j4);
        int b = 4 * t;
        ls[b + 0] = s4.x; ls[b + 1] = s4.y; ls[b + 2] = s4.z; ls[b + 3] = s4.w;
        if (l4.x == lr) mrow |= 1u << (b + 0);
        if (l4.y == lr) mrow |= 1u << (b + 1);
        if (l4.z == lr) mrow |= 1u << (b + 2);
        if (l4.w == lr) mrow |= 1u << (b + 3);
    }

    #pragma unroll
    for (int q = 0; q < 16; q++) {
        if ((mrow >> q) & 1u) {
            int p = atomicAdd(&mcount, 1);
            if (p < MAXM) { jm[p] = gjf(tid, q); vm[p] = ls[q]; cnt[p] = 0; }
        }
    }
    __syncthreads();
    int k = mcount;
    if (k > MAXM) k = MAXM;

    for (int m = 0; m < k; m++) {
        float vmv = vm[m];
        int jmi = jm[m];
        int c = 0;
        #pragma unroll
        for (int q = 0; q < 16; q++)
            c += (ls[q] > vmv || (ls[q] == vmv && gjf(tid, q) < jmi)) ? 1 : 0;
        c = __reduce_add_sync(0xffffffffu, c);
        if (lane == 0) atomicAdd(&cnt[m], c);
    }

    {
        float lval = NEG_INF;
        int lpack = PMAX, lq = 0;
        #pragma unroll
        for (int q = 0; q < 16; q++) {
            float v = ls[q];
            int p = (gjf(tid, q) << 1) | ((mrow >> q) & 1);
            if (v > lval || (v == lval && p < lpack)) { lval = v; lpack = p; lq = q; }
        }
        for (int e = 0; e < k; e++) {
            float bv = lval;
            int bp = lpack;
            #pragma unroll
            for (int o = 16; o; o >>= 1) {
                float ov = __shfl_xor_sync(0xffffffffu, bv, o);
                int op = __shfl_xor_sync(0xffffffffu, bp, o);
                if (ov > bv || (ov == bv && op < bp)) { bv = ov; bp = op; }
            }
            if (lane == 0) { wv[wid][e] = bv; wj[wid][e] = bp; }
            if (lpack == bp) {
                ls[lq] = NEG_INF;
                lval = NEG_INF; lpack = PMAX; lq = 0;
                #pragma unroll
                for (int q = 0; q < 16; q++) {
                    float v = ls[q];
                    int p = (gjf(tid, q) << 1) | ((mrow >> q) & 1);
                    if (v > lval || (v == lval && p < lpack)) { lval = v; lpack = p; lq = q; }
                }
            }
        }
    }
    __syncthreads();

    if (tid == 0) {
        int h[8] = {0, 0, 0, 0, 0, 0, 0, 0};
        float kf = (float)k;
        float fp_acc = 0.0f;
        for (int e = 1; e <= k; e++) {
            float bv = NEG_INF;
            int bp = PMAX, bw = 0;
            #pragma unroll
            for (int w = 0; w < 8; w++) {
                if (h[w] < k) {
                    float v = wv[w][h[w]];
                    int p = wj[w][h[w]];
                    if (v > bv || (v == bv && p < bp)) { bv = v; bp = p; bw = w; }
                }
            }
            h[bw]++;
            if (!(bp & 1))
                fp_acc += bv * (0.5f + (kf - (float)e + 1.0f) / kf * 0.5f);
        }
        float fn_acc = 0.0f;
        float nf = (float)NB;
        for (int m = 0; m < k; m++) {
            int rank = cnt[m] + 1;
            if (rank > k)
                fn_acc += vm[m] * (0.5f + ((float)rank - kf) / (nf - kf) * 0.5f);
        }
        g_partial[row] = fp_acc - fn_acc;
    }
}

__global__ void out_kernel(float* out) {
    __shared__ double red[256];
    int tid = threadIdx.x;
    double s = 0.0;
    #pragma unroll
    for (int t = 0; t < 16; t++) s += (double)g_partial[tid + 256 * t];
    red[tid] = s;
    __syncthreads();
    for (int o = 128; o; o >>= 1) {
        if (tid < o) red[tid] += red[tid + o];
        __syncthreads();
    }
    if (tid == 0) out[0] = (float)red[0];
}

extern "C" void kernel_launch(void* const* d_in, const int* in_sizes, int n_in,
                              void* d_out, int out_size) {
    const float* X = (const float*)d_in[0];
    const int* labels = (const int*)d_in[1];
    float* out = (float*)d_out;

    prep_kernel<<<NB / 8, 256>>>(X);
    gemm_mma_kernel<<<528, 256>>>(labels);
    phaseB_kernel<<<NB, 256>>>(labels);
    out_kernel<<<1, 256>>>(out);
}

// round 16
// speedup vs baseline: 1.1705x; 1.0167x over previous
#include <cuda_runtime.h>
#include <cuda_bf16.h>
#include <math.h>

#define NB 4096
#define ND 128
#define LDA 40
#define MAXM 64
#define MARGINF 0.2f

__device__ __align__(16) float g_sq[NB];
__device__ __align__(16) float g_partial[NB];
__device__ __align__(16) float g_sim[(size_t)NB * NB];            // 64 MB
__device__ __align__(16) __nv_bfloat16 g_Xhi[(size_t)NB * ND];    // 1 MB
__device__ __align__(16) __nv_bfloat16 g_Xlo[(size_t)NB * ND];    // 1 MB

// ---------------- Kernel 1: norms + bf16 hi/lo split ----------------
__global__ void prep_kernel(const float* __restrict__ X) {
    int row = blockIdx.x * 8 + (threadIdx.x >> 5);
    int lane = threadIdx.x & 31;
    float4 v = ((const float4*)(X + (size_t)row * ND))[lane];
    float s = v.x * v.x + v.y * v.y + v.z * v.z + v.w * v.w;
    #pragma unroll
    for (int o = 16; o; o >>= 1) s += __shfl_xor_sync(0xffffffffu, s, o);
    if (lane == 0) g_sq[row] = s;
    __nv_bfloat16 h0 = __float2bfloat16(v.x), h1 = __float2bfloat16(v.y);
    __nv_bfloat16 h2 = __float2bfloat16(v.z), h3 = __float2bfloat16(v.w);
    __nv_bfloat16 l0 = __float2bfloat16(v.x - __bfloat162float(h0));
    __nv_bfloat16 l1 = __float2bfloat16(v.y - __bfloat162float(h1));
    __nv_bfloat16 l2 = __float2bfloat16(v.z - __bfloat162float(h2));
    __nv_bfloat16 l3 = __float2bfloat16(v.w - __bfloat162float(h3));
    size_t base = (size_t)row * ND + 4 * lane;
    ((__nv_bfloat162*)(g_Xhi + base))[0] = __nv_bfloat162(h0, h1);
    ((__nv_bfloat162*)(g_Xhi + base))[1] = __nv_bfloat162(h2, h3);
    ((__nv_bfloat162*)(g_Xlo + base))[0] = __nv_bfloat162(l0, l1);
    ((__nv_bfloat162*)(g_Xlo + base))[1] = __nv_bfloat162(l2, l3);
}

__device__ __forceinline__ float mksim(float si, float sj, float dot, bool mt) {
    float d2 = fmaxf(si + sj - 2.0f * dot, 0.0f);
    float s = (d2 == 0.0f) ? 0.0f : -sqrtf(d2);
    return mt ? s : s + MARGINF;
}

// ---------------- Kernel 2: mma.sync bf16 split-GEMM -> sim ----------------
// Symmetric: 528 upper-triangular 128x128 tiles; off-diagonal tiles also
// mirror-store the transpose. 256 thr, warp tile 32x64, K=384 (hi.hi +
// hi.lo + lo.hi), 12 double-buffered K=32 chunks.
__global__ __launch_bounds__(256, 2)
void gemm_mma_kernel(const int* __restrict__ labels) {
    int t = blockIdx.x;
    int bi = 0;
    while ((bi + 1) * (65 - (bi + 1)) / 2 <= t) bi++;
    int bj = bi + (t - bi * (65 - bi) / 2);

    __shared__ __align__(16) __nv_bfloat16 Asm[2][128 * LDA];
    __shared__ __align__(16) __nv_bfloat16 Bsm[2][128 * LDA];
    __shared__ float sqA[128], sqB[128];
    __shared__ int lbA[128], lbB[128];

    int tid = threadIdx.x, lane = tid & 31, wid = tid >> 5;
    int rowA = bi * 128, rowB = bj * 128;

    if (tid < 128) {
        sqA[tid] = g_sq[rowA + tid];
        lbA[tid] = labels[rowA + tid];
    } else {
        int tt = tid - 128;
        sqB[tt] = g_sq[rowB + tt];
        lbB[tt] = labels[rowB + tt];
    }

    int lrow = tid >> 1, lhalf = tid & 1;
    int wm = (wid & 3) * 32, wn = (wid >> 2) * 64;
    int ar = (lane & 7) + 8 * ((lane >> 3) & 1);
    int ac = 8 * (lane >> 4);
    int br = (lane & 7) + 8 * ((lane >> 4) & 1);
    int bc = 8 * ((lane >> 3) & 1);

    float d[2][8][4];
    #pragma unroll
    for (int mi = 0; mi < 2; mi++)
        #pragma unroll
        for (int nj = 0; nj < 8; nj++)
            #pragma unroll
            for (int q = 0; q < 4; q++) d[mi][nj][q] = 0.0f;

    uint4 arg0, arg1, brg0, brg1;
    {
        const uint4* As = (const uint4*)(g_Xhi + (size_t)(rowA + lrow) * ND + 16 * lhalf);
        const uint4* Bs = (const uint4*)(g_Xhi + (size_t)(rowB + lrow) * ND + 16 * lhalf);
        arg0 = As[0]; arg1 = As[1];
        brg0 = Bs[0]; brg1 = Bs[1];
    }
    ((uint4*)(Asm[0] + lrow * LDA + 16 * lhalf))[0] = arg0;
    ((uint4*)(Asm[0] + lrow * LDA + 16 * lhalf))[1] = arg1;
    ((uint4*)(Bsm[0] + lrow * LDA + 16 * lhalf))[0] = brg0;
    ((uint4*)(Bsm[0] + lrow * LDA + 16 * lhalf))[1] = brg1;
    __syncthreads();

    #pragma unroll
    for (int c = 0; c < 12; c++) {
        int cur = c & 1;
        if (c < 11) {
            int cn = c + 1;
            int seg = cn >> 2, k0 = (cn & 3) * 32;
            const __nv_bfloat16* Aps = (seg < 2) ? g_Xhi : g_Xlo;   // hi,hi,lo
            const __nv_bfloat16* Bps = (seg == 1) ? g_Xlo : g_Xhi;  // hi,lo,hi
            const uint4* As = (const uint4*)(Aps + (size_t)(rowA + lrow) * ND + k0 + 16 * lhalf);
            const uint4* Bs = (const uint4*)(Bps + (size_t)(rowB + lrow) * ND + k0 + 16 * lhalf);
            arg0 = As[0]; arg1 = As[1];
            brg0 = Bs[0]; brg1 = Bs[1];
        }
        unsigned sA = (unsigned)__cvta_generic_to_shared(Asm[cur]);
        unsigned sB = (unsigned)__cvta_generic_to_shared(Bsm[cur]);
        #pragma unroll
        for (int ks = 0; ks < 2; ks++) {
            unsigned a_[2][4], b_[8][2];
            #pragma unroll
            for (int mi = 0; mi < 2; mi++) {
                unsigned ad = sA + 2u * (unsigned)((wm + mi * 16 + ar) * LDA + ks * 16 + ac);
                asm volatile(
                    "ldmatrix.sync.aligned.m8n8.x4.shared.b16 {%0,%1,%2,%3}, [%4];"
                    : "=r"(a_[mi][0]), "=r"(a_[mi][1]), "=r"(a_[mi][2]), "=r"(a_[mi][3])
                    : "r"(ad));
            }
            #pragma unroll
            for (int np = 0; np < 4; np++) {
                unsigned bd = sB + 2u * (unsigned)((wn + np * 16 + br) * LDA + ks * 16 + bc);
                asm volatile(
                    "ldmatrix.sync.aligned.m8n8.x4.shared.b16 {%0,%1,%2,%3}, [%4];"
                    : "=r"(b_[2 * np][0]), "=r"(b_[2 * np][1]),
                      "=r"(b_[2 * np + 1][0]), "=r"(b_[2 * np + 1][1])
                    : "r"(bd));
            }
            #pragma unroll
            for (int mi = 0; mi < 2; mi++)
                #pragma unroll
                for (int nj = 0; nj < 8; nj++)
                    asm volatile(
                        "mma.sync.aligned.m16n8k16.row.col.f32.bf16.bf16.f32 "
                        "{%0,%1,%2,%3},{%4,%5,%6,%7},{%8,%9},{%0,%1,%2,%3};"
                        : "+f"(d[mi][nj][0]), "+f"(d[mi][nj][1]),
                          "+f"(d[mi][nj][2]), "+f"(d[mi][nj][3])
                        : "r"(a_[mi][0]), "r"(a_[mi][1]), "r"(a_[mi][2]), "r"(a_[mi][3]),
                          "r"(b_[nj][0]), "r"(b_[nj][1]));
        }
        if (c < 11) {
            int nxt = cur ^ 1;
            ((uint4*)(Asm[nxt] + lrow * LDA + 16 * lhalf))[0] = arg0;
            ((uint4*)(Asm[nxt] + lrow * LDA + 16 * lhalf))[1] = arg1;
            ((uint4*)(Bsm[nxt] + lrow * LDA + 16 * lhalf))[0] = brg0;
            ((uint4*)(Bsm[nxt] + lrow * LDA + 16 * lhalf))[1] = brg1;
        }
        __syncthreads();
    }

    int gid = lane >> 2, tig = lane & 3;
    #pragma unroll
    for (int mi = 0; mi < 2; mi++) {
        #pragma unroll
        for (int half = 0; half < 2; half++) {
            int ml = wm + mi * 16 + gid + 8 * half;
            float sa = sqA[ml];
            int la = lbA[ml];
            float* dst = g_sim + (size_t)(rowA + ml) * NB + rowB;
            #pragma unroll
            for (int nj = 0; nj < 8; nj++) {
                int nl = wn + nj * 8 + 2 * tig;
                float2 o;
                o.x = mksim(sa, sqB[nl],     d[mi][nj][2 * half],     la == lbB[nl]);
                o.y = mksim(sa, sqB[nl + 1], d[mi][nj][2 * half + 1], la == lbB[nl + 1]);
                *(float2*)(dst + nl) = o;
                if (bi != bj) {
                    g_sim[(size_t)(rowB + nl) * NB + rowA + ml] = o.x;
                    g_sim[(size_t)(rowB + nl + 1) * NB + rowA + ml] = o.y;
                }
            }
        }
    }
}

// ---------------- Kernel 3: per-row rank-aware selection ----------------
// Threshold-based per-warp top-k: NO array mutation, NO dynamic indexing ->
// ls[16] stays register-resident (the R11-R15 versions demoted it to local
// memory via ls[lq] dynamic writes).
__device__ __forceinline__ int gjf(int tid, int q) {
    return 4 * tid + 1024 * (q >> 2) + (q & 3);
}

__global__ __launch_bounds__(256)
void phaseB_kernel(const int* __restrict__ labels) {
    __shared__ float vm[MAXM];
    __shared__ int jm[MAXM];
    __shared__ int cnt[MAXM];
    __shared__ float wv[8][MAXM];
    __shared__ int   wj[8][MAXM];
    __shared__ int mcount;

    const float NEG_INF = __int_as_float(0xff800000);
    const float POS_INF = __int_as_float(0x7f800000);
    const int   PMAX = 0x7fffffff;
    int tid = threadIdx.x, lane = tid & 31, wid = tid >> 5;
    int row = blockIdx.x;
    const float* simr = g_sim + (size_t)row * NB;
    int lr = labels[row];
    if (tid == 0) mcount = 0;
    __syncthreads();

    float ls[16];
    unsigned mrow = 0;
    #pragma unroll
    for (int t = 0; t < 4; t++) {
        int j4 = tid + 256 * t;
        float4 s4 = *(const float4*)(simr + 4 * (size_t)j4);
        int4 l4 = *(const int4*)(labels + 4 * j4);
        int b = 4 * t;
        ls[b + 0] = s4.x; ls[b + 1] = s4.y; ls[b + 2] = s4.z; ls[b + 3] = s4.w;
        if (l4.x == lr) mrow |= 1u << (b + 0);
        if (l4.y == lr) mrow |= 1u << (b + 1);
        if (l4.z == lr) mrow |= 1u << (b + 2);
        if (l4.w == lr) mrow |= 1u << (b + 3);
    }

    // Gather matched elements.
    #pragma unroll
    for (int q = 0; q < 16; q++) {
        if ((mrow >> q) & 1u) {
            int p = atomicAdd(&mcount, 1);
            if (p < MAXM) { jm[p] = gjf(tid, q); vm[p] = ls[q]; cnt[p] = 0; }
        }
    }
    __syncthreads();
    int k = mcount;
    if (k > MAXM) k = MAXM;

    // Count-based ranks for matched elements (rank = cnt+1, stable ties).
    for (int m = 0; m < k; m++) {
        float vmv = vm[m];
        int jmi = jm[m];
        int c = 0;
        #pragma unroll
        for (int q = 0; q < 16; q++)
            c += (ls[q] > vmv || (ls[q] == vmv && gjf(tid, q) < jmi)) ? 1 : 0;
        c = __reduce_add_sync(0xffffffffu, c);
        if (lane == 0) atomicAdd(&cnt[m], c);
    }

    // Per-warp top-k via descending-threshold selection (pure compares, no
    // clears): step e selects max over elements strictly after (tv, tp) in
    // the stable order (v desc, packed-idx asc).
    {
        float tv = POS_INF;
        int tp = -1;
        for (int e = 0; e < k; e++) {
            float bv = NEG_INF;
            int bp = PMAX;
            #pragma unroll
            for (int q = 0; q < 16; q++) {
                float v = ls[q];
                int p = (gjf(tid, q) << 1) | (int)((mrow >> q) & 1);
                bool after = (v < tv) || (v == tv && p > tp);
                bool better = (v > bv) || (v == bv && p < bp);
                if (after && better) { bv = v; bp = p; }
            }
            #pragma unroll
            for (int o = 16; o; o >>= 1) {
                float ov = __shfl_xor_sync(0xffffffffu, bv, o);
                int op = __shfl_xor_sync(0xffffffffu, bp, o);
                if (ov > bv || (ov == bv && op < bp)) { bv = ov; bp = op; }
            }
            if (lane == 0) { wv[wid][e] = bv; wj[wid][e] = bp; }
            tv = bv; tp = bp;
        }
    }
    __syncthreads();

    // Thread 0: 8-way merge of sorted warp lists -> global top-k, fp term;
    // then fn term from count-ranks; write per-row partial.
    if (tid == 0) {
        int h[8] = {0, 0, 0, 0, 0, 0, 0, 0};
        float kf = (float)k;
        float fp_acc = 0.0f;
        for (int e = 1; e <= k; e++) {
            float bv = NEG_INF;
            int bp = PMAX, bw = 0;
            #pragma unroll
            for (int w = 0; w < 8; w++) {
                if (h[w] < k) {
                    float v = wv[w][h[w]];
                    int p = wj[w][h[w]];
                    if (v > bv || (v == bv && p < bp)) { bv = v; bp = p; bw = w; }
                }
            }
            h[bw]++;
            if (!(bp & 1))
                fp_acc += bv * (0.5f + (kf - (float)e + 1.0f) / kf * 0.5f);
        }
        float fn_acc = 0.0f;
        float nf = (float)NB;
        for (int m = 0; m < k; m++) {
            int rank = cnt[m] + 1;
            if (rank > k)
                fn_acc += vm[m] * (0.5f + ((float)rank - kf) / (nf - kf) * 0.5f);
        }
        g_partial[row] = fp_acc - fn_acc;
    }
}

__global__ void out_kernel(float* out) {
    __shared__ double red[256];
    int tid = threadIdx.x;
    double s = 0.0;
    #pragma unroll
    for (int t = 0; t < 16; t++) s += (double)g_partial[tid + 256 * t];
    red[tid] = s;
    __syncthreads();
    for (int o = 128; o; o >>= 1) {
        if (tid < o) red[tid] += red[tid + o];
        __syncthreads();
    }
    if (tid == 0) out[0] = (float)red[0];
}

extern "C" void kernel_launch(void* const* d_in, const int* in_sizes, int n_in,
                              void* d_out, int out_size) {
    const float* X = (const float*)d_in[0];
    const int* labels = (const int*)d_in[1];
    float* out = (float*)d_out;

    prep_kernel<<<NB / 8, 256>>>(X);
    gemm_mma_kernel<<<528, 256>>>(labels);
    phaseB_kernel<<<NB, 256>>>(labels);
    out_kernel<<<1, 256>>>(out);
}